// round 5
// baseline (speedup 1.0000x reference)
#include <cuda_runtime.h>
#include <cfloat>
#include <math.h>

#define M_TOT 16384   // B*N queries
#define D_IN  1024
#define E_DIM 512
#define K_CB  4096

// Scratch (device globals: no allocation allowed)
__device__ float g_xn[M_TOT * E_DIM];   // proj, then normalized rows (in place)
__device__ float g_cn[K_CB * E_DIM];    // normalized codebook
__device__ float g_cnn[K_CB];           // sum(cn*cn) per codeword

// ---- packed fp32x2 helpers (Blackwell FFMA2; bit-exact 2x scalar fp32 FMA) ----
__device__ __forceinline__ void fma2(unsigned long long& d,
                                     unsigned long long a,
                                     unsigned long long b) {
    asm("fma.rn.f32x2 %0, %1, %2, %0;" : "+l"(d) : "l"(a), "l"(b));
}
__device__ __forceinline__ unsigned long long dup2(float x) {
    unsigned long long r;
    asm("mov.b64 %0, {%1, %1};" : "=l"(r) : "f"(x));
    return r;
}
__device__ __forceinline__ float2 unpack2(unsigned long long v) {
    float2 f;
    asm("mov.b64 {%0, %1}, %2;" : "=f"(f.x), "=f"(f.y) : "l"(v));
    return f;
}

// ---------------------------------------------------------------------------
// Kernel 1: projection GEMM  g_xn[M,E] = X[M,D] @ W[D,E]
// BM=128, BN=64, BK=16, 256 threads; FFMA2 over m-pairs (8m x 4n per thread)
// ---------------------------------------------------------------------------
__global__ void proj_gemm_kernel(const float* __restrict__ X,
                                 const float* __restrict__ W) {
    __shared__ float As[16 * 132];   // [k][m], padded
    __shared__ float Bs[16 * 64];    // [k][n]
    const int tx = threadIdx.x & 15;
    const int ty = threadIdx.x >> 4;
    const int m0 = blockIdx.y * 128;
    const int n0 = blockIdx.x * 64;

    unsigned long long acc[4][4];    // [m-pair][n], each holds 2 m-rows
    #pragma unroll
    for (int i = 0; i < 4; i++)
        #pragma unroll
        for (int j = 0; j < 4; j++) acc[i][j] = 0ull;

    for (int kt = 0; kt < D_IN; kt += 16) {
        #pragma unroll
        for (int t = 0; t < 2; t++) {
            int f   = threadIdx.x * 2 + t;   // 0..511
            int row = f >> 2;                // 0..127
            int c4  = f & 3;                 // 0..3
            float4 v = *(const float4*)(X + (size_t)(m0 + row) * D_IN + kt + c4 * 4);
            As[(c4 * 4 + 0) * 132 + row] = v.x;
            As[(c4 * 4 + 1) * 132 + row] = v.y;
            As[(c4 * 4 + 2) * 132 + row] = v.z;
            As[(c4 * 4 + 3) * 132 + row] = v.w;
        }
        {
            int f  = threadIdx.x;            // 0..255
            int k  = f >> 4;
            int c4 = f & 15;
            float4 v = *(const float4*)(W + (size_t)(kt + k) * E_DIM + n0 + c4 * 4);
            *(float4*)(Bs + k * 64 + c4 * 4) = v;
        }
        __syncthreads();

        #pragma unroll
        for (int k = 0; k < 16; k++) {
            // a: 8 m-values = 4 packed pairs (contiguous in As)
            ulonglong2 a0 = *(const ulonglong2*)(As + k * 132 + ty * 8);
            ulonglong2 a1 = *(const ulonglong2*)(As + k * 132 + ty * 8 + 4);
            unsigned long long ap[4] = {a0.x, a0.y, a1.x, a1.y};
            float4 b = *(const float4*)(Bs + k * 64 + tx * 4);
            unsigned long long bd[4] = {dup2(b.x), dup2(b.y), dup2(b.z), dup2(b.w)};
            #pragma unroll
            for (int i = 0; i < 4; i++)
                #pragma unroll
                for (int j = 0; j < 4; j++)
                    fma2(acc[i][j], ap[i], bd[j]);
        }
        __syncthreads();
    }

    #pragma unroll
    for (int i = 0; i < 4; i++) {
        float2 u0 = unpack2(acc[i][0]);
        float2 u1 = unpack2(acc[i][1]);
        float2 u2 = unpack2(acc[i][2]);
        float2 u3 = unpack2(acc[i][3]);
        int r0 = m0 + ty * 8 + 2 * i;
        *(float4*)(g_xn + (size_t)r0 * E_DIM + n0 + tx * 4) =
            make_float4(u0.x, u1.x, u2.x, u3.x);
        *(float4*)(g_xn + (size_t)(r0 + 1) * E_DIM + n0 + tx * 4) =
            make_float4(u0.y, u1.y, u2.y, u3.y);
    }
}

// ---------------------------------------------------------------------------
// Kernel 2: normalize rows of g_xn in place
// ---------------------------------------------------------------------------
__global__ void norm_x_kernel() {
    const int row = blockIdx.x;
    float* p = g_xn + (size_t)row * E_DIM;
    float4 v = *(float4*)(p + threadIdx.x * 4);
    float s = v.x * v.x + v.y * v.y + v.z * v.z + v.w * v.w;
    #pragma unroll
    for (int o = 16; o > 0; o >>= 1) s += __shfl_xor_sync(0xFFFFFFFFu, s, o);
    __shared__ float ws[4];
    if ((threadIdx.x & 31) == 0) ws[threadIdx.x >> 5] = s;
    __syncthreads();
    float tot = ws[0] + ws[1] + ws[2] + ws[3];
    float denom = fmaxf(sqrtf(tot), 1e-12f);
    v.x = v.x / denom; v.y = v.y / denom; v.z = v.z / denom; v.w = v.w / denom;
    *(float4*)(p + threadIdx.x * 4) = v;
}

// ---------------------------------------------------------------------------
// Kernel 3: normalize codebook -> g_cn, g_cnn = sum(cn*cn) per row
// ---------------------------------------------------------------------------
__global__ void norm_cb_kernel(const float* __restrict__ CB) {
    const int row = blockIdx.x;
    float4 v = *(const float4*)(CB + (size_t)row * E_DIM + threadIdx.x * 4);
    float s = v.x * v.x + v.y * v.y + v.z * v.z + v.w * v.w;
    #pragma unroll
    for (int o = 16; o > 0; o >>= 1) s += __shfl_xor_sync(0xFFFFFFFFu, s, o);
    __shared__ float ws[4];
    __shared__ float ws2[4];
    if ((threadIdx.x & 31) == 0) ws[threadIdx.x >> 5] = s;
    __syncthreads();
    float tot = ws[0] + ws[1] + ws[2] + ws[3];
    float denom = fmaxf(sqrtf(tot), 1e-12f);
    v.x = v.x / denom; v.y = v.y / denom; v.z = v.z / denom; v.w = v.w / denom;
    *(float4*)(g_cn + (size_t)row * E_DIM + threadIdx.x * 4) = v;
    float s2 = v.x * v.x + v.y * v.y + v.z * v.z + v.w * v.w;
    #pragma unroll
    for (int o = 16; o > 0; o >>= 1) s2 += __shfl_xor_sync(0xFFFFFFFFu, s2, o);
    if ((threadIdx.x & 31) == 0) ws2[threadIdx.x >> 5] = s2;
    __syncthreads();
    if (threadIdx.x == 0) g_cnn[row] = ws2[0] + ws2[1] + ws2[2] + ws2[3];
}

// ---------------------------------------------------------------------------
// Kernel 4: argmax_k ( <cn_k,xn_q> - cnn[k]/2 ) == argmin distance.
// 64 queries/block. FFMA2 inner loop (4q x 8k per thread, k packed in pairs).
// Double-buffered codebook tiles, one barrier per 32-e chunk.
// ---------------------------------------------------------------------------
#define XS_PITCH 68     // multiple of 4 -> LDS.128 on xs reads
#define CS_PITCH 132
#define CS_BUF   (32 * CS_PITCH)
#define SMEM_BYTES ((512 * XS_PITCH + 2 * CS_BUF + 128 + 64 * 16) * 4 + 64 * 16 * 4)

__global__ void __launch_bounds__(256, 1) argmin_kernel(float* __restrict__ out) {
    extern __shared__ float sm[];
    float* xs   = sm;                          // [512][68]  xs[e][q]
    float* cs   = xs + 512 * XS_PITCH;         // 2 x [32][132]  cs[e][k]
    float* cnns = cs + 2 * CS_BUF;             // [128]
    float* rv   = cnns + 128;                  // [64][16]
    int*   ri   = (int*)(rv + 64 * 16);        // [64][16]

    const int tx = threadIdx.x & 15;
    const int ty = threadIdx.x >> 4;
    const int q0 = blockIdx.x * 64;

    // query tile, transposed into xs[e][q]
    #pragma unroll 4
    for (int t = 0; t < 32; t++) {
        int f = threadIdx.x + t * 256;     // 0..8191
        int q = f >> 7;                    // 0..63
        int e4 = f & 127;                  // 0..127
        float4 v = *(const float4*)(g_xn + (size_t)(q0 + q) * E_DIM + e4 * 4);
        xs[(e4 * 4 + 0) * XS_PITCH + q] = v.x;
        xs[(e4 * 4 + 1) * XS_PITCH + q] = v.y;
        xs[(e4 * 4 + 2) * XS_PITCH + q] = v.z;
        xs[(e4 * 4 + 3) * XS_PITCH + q] = v.w;
    }

    const int lk  = threadIdx.x >> 3;       // 0..31  (k-slot for cs loads, x8)
    const int le4 = threadIdx.x & 7;        // 0..7   (e4 for cs loads)

    float bestv[4] = {-INFINITY, -INFINITY, -INFINITY, -INFINITY};
    int   besti[4] = {0, 0, 0, 0};

    for (int kc = 0; kc < K_CB; kc += 128) {
        __syncthreads();   // xs store (first iter) / previous kc readers done
        if (threadIdx.x < 128) cnns[threadIdx.x] = g_cnn[kc + threadIdx.x];

        // load tile et=0 into buffer 0
        #pragma unroll
        for (int t = 0; t < 4; t++) {
            int k = lk + t * 32;
            float4 v = *(const float4*)(g_cn + (size_t)(kc + k) * E_DIM + le4 * 4);
            float* dst = cs;
            dst[(le4 * 4 + 0) * CS_PITCH + k] = v.x;
            dst[(le4 * 4 + 1) * CS_PITCH + k] = v.y;
            dst[(le4 * 4 + 2) * CS_PITCH + k] = v.z;
            dst[(le4 * 4 + 3) * CS_PITCH + k] = v.w;
        }
        __syncthreads();

        unsigned long long acc[4][4];    // [q][k-pair]; pairs: (tx*4+2p) and (64+tx*4+2p)
        #pragma unroll
        for (int i = 0; i < 4; i++)
            #pragma unroll
            for (int j = 0; j < 4; j++) acc[i][j] = 0ull;

        for (int et = 0; et < 16; et++) {
            const float* cur = cs + (et & 1) * CS_BUF;

            // prefetch next e-tile into registers (overlaps with compute)
            float4 pf[4];
            if (et < 15) {
                #pragma unroll
                for (int t = 0; t < 4; t++) {
                    int k = lk + t * 32;
                    pf[t] = *(const float4*)(g_cn + (size_t)(kc + k) * E_DIM +
                                             (et + 1) * 32 + le4 * 4);
                }
            }

            #pragma unroll
            for (int e = 0; e < 32; e++) {
                const int eg = et * 32 + e;
                float4 xav = *(const float4*)(xs + eg * XS_PITCH + ty * 4);
                unsigned long long xa2[4] = {dup2(xav.x), dup2(xav.y),
                                             dup2(xav.z), dup2(xav.w)};
                ulonglong2 c0 = *(const ulonglong2*)(cur + e * CS_PITCH + tx * 4);
                ulonglong2 c1 = *(const ulonglong2*)(cur + e * CS_PITCH + 64 + tx * 4);
                #pragma unroll
                for (int i = 0; i < 4; i++) {
                    fma2(acc[i][0], xa2[i], c0.x);
                    fma2(acc[i][1], xa2[i], c0.y);
                    fma2(acc[i][2], xa2[i], c1.x);
                    fma2(acc[i][3], xa2[i], c1.y);
                }
            }

            if (et < 15) {
                float* nxt = cs + ((et + 1) & 1) * CS_BUF;
                #pragma unroll
                for (int t = 0; t < 4; t++) {
                    int k = lk + t * 32;
                    nxt[(le4 * 4 + 0) * CS_PITCH + k] = pf[t].x;
                    nxt[(le4 * 4 + 1) * CS_PITCH + k] = pf[t].y;
                    nxt[(le4 * 4 + 2) * CS_PITCH + k] = pf[t].z;
                    nxt[(le4 * 4 + 3) * CS_PITCH + k] = pf[t].w;
                }
            }
            __syncthreads();
        }

        // score update: maximize dot - cnn/2; strict > keeps earliest index
        #pragma unroll
        for (int i = 0; i < 4; i++) {
            #pragma unroll
            for (int j = 0; j < 4; j++) {
                float2 u = unpack2(acc[i][j]);
                int kb = (j < 2) ? (tx * 4 + 2 * j) : (64 + tx * 4 + 2 * (j - 2));
                float s0 = u.x - 0.5f * cnns[kb];
                float s1 = u.y - 0.5f * cnns[kb + 1];
                if (s0 > bestv[i]) { bestv[i] = s0; besti[i] = kc + kb; }
                if (s1 > bestv[i]) { bestv[i] = s1; besti[i] = kc + kb + 1; }
            }
        }
    }

    __syncthreads();
    #pragma unroll
    for (int i = 0; i < 4; i++) {
        int q = ty * 4 + i;
        rv[q * 16 + tx] = bestv[i];
        ri[q * 16 + tx] = besti[i];
    }
    __syncthreads();
    if (threadIdx.x < 64) {
        int q = threadIdx.x;
        float bv = rv[q * 16];
        int   bi = ri[q * 16];
        #pragma unroll
        for (int t = 1; t < 16; t++) {
            float v  = rv[q * 16 + t];
            int   ix = ri[q * 16 + t];
            if (v > bv || (v == bv && ix < bi)) { bv = v; bi = ix; }
        }
        out[q0 + q] = (float)bi;   // output dtype: float32
    }
}

// ---------------------------------------------------------------------------
extern "C" void kernel_launch(void* const* d_in, const int* in_sizes, int n_in,
                              void* d_out, int out_size) {
    const float* x  = nullptr;
    const float* w  = nullptr;
    const float* cb = nullptr;
    for (int i = 0; i < n_in; i++) {
        if (in_sizes[i] == M_TOT * D_IN)       x  = (const float*)d_in[i];
        else if (in_sizes[i] == D_IN * E_DIM)  w  = (const float*)d_in[i];
        else if (in_sizes[i] == K_CB * E_DIM)  cb = (const float*)d_in[i];
    }
    float* out = (float*)d_out;

    dim3 g1(E_DIM / 64, M_TOT / 128);   // (8, 128)
    proj_gemm_kernel<<<g1, 256>>>(x, w);
    norm_x_kernel<<<M_TOT, 128>>>();
    norm_cb_kernel<<<K_CB, 128>>>(cb);

    cudaFuncSetAttribute(argmin_kernel,
                         cudaFuncAttributeMaxDynamicSharedMemorySize, SMEM_BYTES);
    argmin_kernel<<<M_TOT / 64, 256, SMEM_BYTES>>>(out);
}

// round 6
// speedup vs baseline: 1.1332x; 1.1332x over previous
#include <cuda_runtime.h>
#include <cfloat>
#include <math.h>

#define M_TOT 16384   // B*N queries
#define D_IN  1024
#define E_DIM 512
#define K_CB  4096

// Scratch (device globals: no allocation allowed)
__device__ float g_xn[M_TOT * E_DIM];    // proj, then normalized rows (in place)
__device__ float g_cnT[E_DIM * K_CB];    // normalized codebook, TRANSPOSED [e][k]
__device__ float g_cnn[K_CB];            // sum(cn*cn) per codeword

// ---- packed fp32x2 helpers (FFMA2; bit-exact 2x scalar fp32 FMA) ----
__device__ __forceinline__ void fma2(unsigned long long& d,
                                     unsigned long long a,
                                     unsigned long long b) {
    asm("fma.rn.f32x2 %0, %1, %2, %0;" : "+l"(d) : "l"(a), "l"(b));
}
__device__ __forceinline__ unsigned long long dup2(float x) {
    unsigned long long r;
    asm("mov.b64 %0, {%1, %1};" : "=l"(r) : "f"(x));
    return r;
}
__device__ __forceinline__ float2 unpack2(unsigned long long v) {
    float2 f;
    asm("mov.b64 {%0, %1}, %2;" : "=f"(f.x), "=f"(f.y) : "l"(v));
    return f;
}

// ---------------------------------------------------------------------------
// Kernel 1: projection GEMM  g_xn[M,E] = X[M,D] @ W[D,E]
// BM=128, BN=64, BK=16, 256 threads; FFMA2 over m-pairs (8m x 4n per thread)
// ---------------------------------------------------------------------------
__global__ void proj_gemm_kernel(const float* __restrict__ X,
                                 const float* __restrict__ W) {
    __shared__ float As[16 * 132];   // [k][m], padded
    __shared__ float Bs[16 * 64];    // [k][n]
    const int tx = threadIdx.x & 15;
    const int ty = threadIdx.x >> 4;
    const int m0 = blockIdx.y * 128;
    const int n0 = blockIdx.x * 64;

    unsigned long long acc[4][4];    // [m-pair][n]
    #pragma unroll
    for (int i = 0; i < 4; i++)
        #pragma unroll
        for (int j = 0; j < 4; j++) acc[i][j] = 0ull;

    for (int kt = 0; kt < D_IN; kt += 16) {
        #pragma unroll
        for (int t = 0; t < 2; t++) {
            int f   = threadIdx.x * 2 + t;   // 0..511
            int row = f >> 2;                // 0..127
            int c4  = f & 3;                 // 0..3
            float4 v = *(const float4*)(X + (size_t)(m0 + row) * D_IN + kt + c4 * 4);
            As[(c4 * 4 + 0) * 132 + row] = v.x;
            As[(c4 * 4 + 1) * 132 + row] = v.y;
            As[(c4 * 4 + 2) * 132 + row] = v.z;
            As[(c4 * 4 + 3) * 132 + row] = v.w;
        }
        {
            int f  = threadIdx.x;            // 0..255
            int k  = f >> 4;
            int c4 = f & 15;
            float4 v = *(const float4*)(W + (size_t)(kt + k) * E_DIM + n0 + c4 * 4);
            *(float4*)(Bs + k * 64 + c4 * 4) = v;
        }
        __syncthreads();

        #pragma unroll
        for (int k = 0; k < 16; k++) {
            ulonglong2 a0 = *(const ulonglong2*)(As + k * 132 + ty * 8);
            ulonglong2 a1 = *(const ulonglong2*)(As + k * 132 + ty * 8 + 4);
            unsigned long long ap[4] = {a0.x, a0.y, a1.x, a1.y};
            float4 b = *(const float4*)(Bs + k * 64 + tx * 4);
            unsigned long long bd[4] = {dup2(b.x), dup2(b.y), dup2(b.z), dup2(b.w)};
            #pragma unroll
            for (int i = 0; i < 4; i++)
                #pragma unroll
                for (int j = 0; j < 4; j++)
                    fma2(acc[i][j], ap[i], bd[j]);
        }
        __syncthreads();
    }

    #pragma unroll
    for (int i = 0; i < 4; i++) {
        float2 u0 = unpack2(acc[i][0]);
        float2 u1 = unpack2(acc[i][1]);
        float2 u2 = unpack2(acc[i][2]);
        float2 u3 = unpack2(acc[i][3]);
        int r0 = m0 + ty * 8 + 2 * i;
        *(float4*)(g_xn + (size_t)r0 * E_DIM + n0 + tx * 4) =
            make_float4(u0.x, u1.x, u2.x, u3.x);
        *(float4*)(g_xn + (size_t)(r0 + 1) * E_DIM + n0 + tx * 4) =
            make_float4(u0.y, u1.y, u2.y, u3.y);
    }
}

// ---------------------------------------------------------------------------
// Kernel 2: normalize rows of g_xn in place
// ---------------------------------------------------------------------------
__global__ void norm_x_kernel() {
    const int row = blockIdx.x;
    float* p = g_xn + (size_t)row * E_DIM;
    float4 v = *(float4*)(p + threadIdx.x * 4);
    float s = v.x * v.x + v.y * v.y + v.z * v.z + v.w * v.w;
    #pragma unroll
    for (int o = 16; o > 0; o >>= 1) s += __shfl_xor_sync(0xFFFFFFFFu, s, o);
    __shared__ float ws[4];
    if ((threadIdx.x & 31) == 0) ws[threadIdx.x >> 5] = s;
    __syncthreads();
    float tot = ws[0] + ws[1] + ws[2] + ws[3];
    float denom = fmaxf(sqrtf(tot), 1e-12f);
    v.x = v.x / denom; v.y = v.y / denom; v.z = v.z / denom; v.w = v.w / denom;
    *(float4*)(p + threadIdx.x * 4) = v;
}

// ---------------------------------------------------------------------------
// Kernel 3: normalize codebook -> g_cnT (transposed), g_cnn
// ---------------------------------------------------------------------------
__global__ void norm_cb_kernel(const float* __restrict__ CB) {
    const int row = blockIdx.x;     // codeword k
    float4 v = *(const float4*)(CB + (size_t)row * E_DIM + threadIdx.x * 4);
    float s = v.x * v.x + v.y * v.y + v.z * v.z + v.w * v.w;
    #pragma unroll
    for (int o = 16; o > 0; o >>= 1) s += __shfl_xor_sync(0xFFFFFFFFu, s, o);
    __shared__ float ws[4];
    __shared__ float ws2[4];
    if ((threadIdx.x & 31) == 0) ws[threadIdx.x >> 5] = s;
    __syncthreads();
    float tot = ws[0] + ws[1] + ws[2] + ws[3];
    float denom = fmaxf(sqrtf(tot), 1e-12f);
    v.x = v.x / denom; v.y = v.y / denom; v.z = v.z / denom; v.w = v.w / denom;
    int e0 = threadIdx.x * 4;
    g_cnT[(size_t)(e0 + 0) * K_CB + row] = v.x;
    g_cnT[(size_t)(e0 + 1) * K_CB + row] = v.y;
    g_cnT[(size_t)(e0 + 2) * K_CB + row] = v.z;
    g_cnT[(size_t)(e0 + 3) * K_CB + row] = v.w;
    float s2 = v.x * v.x + v.y * v.y + v.z * v.z + v.w * v.w;
    #pragma unroll
    for (int o = 16; o > 0; o >>= 1) s2 += __shfl_xor_sync(0xFFFFFFFFu, s2, o);
    if ((threadIdx.x & 31) == 0) ws2[threadIdx.x >> 5] = s2;
    __syncthreads();
    if (threadIdx.x == 0) g_cnn[row] = ws2[0] + ws2[1] + ws2[2] + ws2[3];
}

// ---------------------------------------------------------------------------
// Kernel 4: argmax_k ( <cn_k,xn_q> - cnn[k]/2 ) == argmin distance.
// 64 queries/block, 512 threads (16 tx x 32 ty), 2q x 8k per thread.
// FFMA2 pairs over k. 128-e codebook chunks, single-buffered.
// ---------------------------------------------------------------------------
#define XS_PITCH 68                     // even, x4 -> vector-friendly
#define EC 128                          // e's per codebook chunk
#define CS_PITCH 132
#define SMEM_BYTES ((512 * XS_PITCH + EC * CS_PITCH + 128 + 64 * 16) * 4 + 64 * 16 * 4)

__global__ void __launch_bounds__(512, 1) argmin_kernel(float* __restrict__ out) {
    extern __shared__ float sm[];
    float* xs   = sm;                          // [512][68]  xs[e][q]
    float* cs   = xs + 512 * XS_PITCH;         // [128][132] cs[e][k]
    float* cnns = cs + EC * CS_PITCH;          // [128]
    float* rv   = cnns + 128;                  // [64][16]
    int*   ri   = (int*)(rv + 64 * 16);        // [64][16]

    const int tid = threadIdx.x;
    const int tx = tid & 15;        // k partition (8 k each)
    const int ty = tid >> 4;        // q partition (2 q each), 0..31
    const int q0 = blockIdx.x * 64;

    // query tile, transposed into xs[e][q]
    #pragma unroll 4
    for (int t = 0; t < 16; t++) {
        int f = tid + t * 512;             // 0..8191
        int q = f >> 7;                    // 0..63
        int e4 = f & 127;                  // 0..127
        float4 v = *(const float4*)(g_xn + (size_t)(q0 + q) * E_DIM + e4 * 4);
        xs[(e4 * 4 + 0) * XS_PITCH + q] = v.x;
        xs[(e4 * 4 + 1) * XS_PITCH + q] = v.y;
        xs[(e4 * 4 + 2) * XS_PITCH + q] = v.z;
        xs[(e4 * 4 + 3) * XS_PITCH + q] = v.w;
    }

    float bestv[2] = {-INFINITY, -INFINITY};
    int   besti[2] = {0, 0};

    for (int kc = 0; kc < K_CB; kc += 128) {
        __syncthreads();   // xs ready (first iter) / prev kc readers done
        if (tid < 128) cnns[tid] = g_cnn[kc + tid];

        unsigned long long acc[2][4];   // [q][k-pair]
        #pragma unroll
        for (int i = 0; i < 2; i++)
            #pragma unroll
            for (int j = 0; j < 4; j++) acc[i][j] = 0ull;

        for (int ec = 0; ec < E_DIM / EC; ec++) {
            // load codebook chunk: EC e-rows x 128 k, coalesced from g_cnT
            #pragma unroll
            for (int t = 0; t < 8; t++) {
                int f  = tid + t * 512;         // 0..4095
                int e  = f >> 5;                // 0..127
                int k4 = f & 31;                // 0..31
                float4 v = *(const float4*)(g_cnT + (size_t)(ec * EC + e) * K_CB +
                                            kc + k4 * 4);
                *(float4*)(cs + e * CS_PITCH + k4 * 4) = v;
            }
            __syncthreads();

            const float* xrow = xs + (ec * EC) * XS_PITCH + ty * 2;
            #pragma unroll 8
            for (int e = 0; e < EC; e++) {
                float2 xq = *(const float2*)(xrow + e * XS_PITCH);
                unsigned long long xa0 = dup2(xq.x);
                unsigned long long xa1 = dup2(xq.y);
                ulonglong2 c0 = *(const ulonglong2*)(cs + e * CS_PITCH + tx * 4);
                ulonglong2 c1 = *(const ulonglong2*)(cs + e * CS_PITCH + 64 + tx * 4);
                fma2(acc[0][0], xa0, c0.x);
                fma2(acc[0][1], xa0, c0.y);
                fma2(acc[0][2], xa0, c1.x);
                fma2(acc[0][3], xa0, c1.y);
                fma2(acc[1][0], xa1, c0.x);
                fma2(acc[1][1], xa1, c0.y);
                fma2(acc[1][2], xa1, c1.x);
                fma2(acc[1][3], xa1, c1.y);
            }
            __syncthreads();
        }

        // score update: maximize dot - cnn/2; strict > keeps earliest index
        #pragma unroll
        for (int i = 0; i < 2; i++) {
            #pragma unroll
            for (int j = 0; j < 4; j++) {
                float2 u = unpack2(acc[i][j]);
                int kb = (j < 2) ? (tx * 4 + 2 * j) : (64 + tx * 4 + 2 * (j - 2));
                float s0 = u.x - 0.5f * cnns[kb];
                float s1 = u.y - 0.5f * cnns[kb + 1];
                if (s0 > bestv[i]) { bestv[i] = s0; besti[i] = kc + kb; }
                if (s1 > bestv[i]) { bestv[i] = s1; besti[i] = kc + kb + 1; }
            }
        }
    }

    __syncthreads();
    #pragma unroll
    for (int i = 0; i < 2; i++) {
        int q = ty * 2 + i;
        rv[q * 16 + tx] = bestv[i];
        ri[q * 16 + tx] = besti[i];
    }
    __syncthreads();
    if (tid < 64) {
        int q = tid;
        float bv = rv[q * 16];
        int   bi = ri[q * 16];
        #pragma unroll
        for (int t = 1; t < 16; t++) {
            float v  = rv[q * 16 + t];
            int   ix = ri[q * 16 + t];
            if (v > bv || (v == bv && ix < bi)) { bv = v; bi = ix; }
        }
        out[q0 + q] = (float)bi;   // output dtype: float32
    }
}

// ---------------------------------------------------------------------------
extern "C" void kernel_launch(void* const* d_in, const int* in_sizes, int n_in,
                              void* d_out, int out_size) {
    const float* x  = nullptr;
    const float* w  = nullptr;
    const float* cb = nullptr;
    for (int i = 0; i < n_in; i++) {
        if (in_sizes[i] == M_TOT * D_IN)       x  = (const float*)d_in[i];
        else if (in_sizes[i] == D_IN * E_DIM)  w  = (const float*)d_in[i];
        else if (in_sizes[i] == K_CB * E_DIM)  cb = (const float*)d_in[i];
    }
    float* out = (float*)d_out;

    dim3 g1(E_DIM / 64, M_TOT / 128);   // (8, 128)
    proj_gemm_kernel<<<g1, 256>>>(x, w);
    norm_x_kernel<<<M_TOT, 128>>>();
    norm_cb_kernel<<<K_CB, 128>>>(cb);

    cudaFuncSetAttribute(argmin_kernel,
                         cudaFuncAttributeMaxDynamicSharedMemorySize, SMEM_BYTES);
    argmin_kernel<<<M_TOT / 64, 512, SMEM_BYTES>>>(out);
}

// round 7
// speedup vs baseline: 1.6982x; 1.4986x over previous
#include <cuda_runtime.h>
#include <cfloat>
#include <math.h>

#define M_TOT 16384   // B*N queries
#define D_IN  1024
#define E_DIM 512
#define K_CB  4096

// Scratch (device globals: no allocation allowed)
__device__ float g_xn[M_TOT * E_DIM];    // proj, then normalized rows (in place)
__device__ float g_cnT[E_DIM * K_CB];    // normalized codebook, TRANSPOSED [e][k]
__device__ float g_cnn[K_CB];            // sum(cn*cn) per codeword

// ---------------------------------------------------------------------------
// Kernel 1: projection GEMM  g_xn[M,E] = X[M,D] @ W[D,E]   (R4 scalar version)
// BM=128, BN=64, BK=16, 256 threads, 8x4 micro-tile per thread
// ---------------------------------------------------------------------------
__global__ void proj_gemm_kernel(const float* __restrict__ X,
                                 const float* __restrict__ W) {
    __shared__ float As[16 * 132];   // [k][m], padded
    __shared__ float Bs[16 * 64];    // [k][n]
    const int tx = threadIdx.x & 15;
    const int ty = threadIdx.x >> 4;
    const int m0 = blockIdx.y * 128;
    const int n0 = blockIdx.x * 64;

    float acc[8][4];
    #pragma unroll
    for (int i = 0; i < 8; i++)
        #pragma unroll
        for (int j = 0; j < 4; j++) acc[i][j] = 0.0f;

    for (int kt = 0; kt < D_IN; kt += 16) {
        #pragma unroll
        for (int t = 0; t < 2; t++) {
            int f   = threadIdx.x * 2 + t;   // 0..511
            int row = f >> 2;                // 0..127
            int c4  = f & 3;                 // 0..3
            float4 v = *(const float4*)(X + (size_t)(m0 + row) * D_IN + kt + c4 * 4);
            As[(c4 * 4 + 0) * 132 + row] = v.x;
            As[(c4 * 4 + 1) * 132 + row] = v.y;
            As[(c4 * 4 + 2) * 132 + row] = v.z;
            As[(c4 * 4 + 3) * 132 + row] = v.w;
        }
        {
            int f  = threadIdx.x;            // 0..255
            int k  = f >> 4;
            int c4 = f & 15;
            float4 v = *(const float4*)(W + (size_t)(kt + k) * E_DIM + n0 + c4 * 4);
            *(float4*)(Bs + k * 64 + c4 * 4) = v;
        }
        __syncthreads();

        #pragma unroll
        for (int k = 0; k < 16; k++) {
            float4 a0 = *(const float4*)(As + k * 132 + ty * 8);
            float4 a1 = *(const float4*)(As + k * 132 + ty * 8 + 4);
            float4 b  = *(const float4*)(Bs + k * 64 + tx * 4);
            float a[8] = {a0.x, a0.y, a0.z, a0.w, a1.x, a1.y, a1.z, a1.w};
            float bb[4] = {b.x, b.y, b.z, b.w};
            #pragma unroll
            for (int i = 0; i < 8; i++)
                #pragma unroll
                for (int j = 0; j < 4; j++)
                    acc[i][j] = fmaf(a[i], bb[j], acc[i][j]);
        }
        __syncthreads();
    }

    #pragma unroll
    for (int i = 0; i < 8; i++) {
        float4 v = make_float4(acc[i][0], acc[i][1], acc[i][2], acc[i][3]);
        *(float4*)(g_xn + (size_t)(m0 + ty * 8 + i) * E_DIM + n0 + tx * 4) = v;
    }
}

// ---------------------------------------------------------------------------
// Kernel 2: normalize rows of g_xn in place
// ---------------------------------------------------------------------------
__global__ void norm_x_kernel() {
    const int row = blockIdx.x;
    float* p = g_xn + (size_t)row * E_DIM;
    float4 v = *(float4*)(p + threadIdx.x * 4);
    float s = v.x * v.x + v.y * v.y + v.z * v.z + v.w * v.w;
    #pragma unroll
    for (int o = 16; o > 0; o >>= 1) s += __shfl_xor_sync(0xFFFFFFFFu, s, o);
    __shared__ float ws[4];
    if ((threadIdx.x & 31) == 0) ws[threadIdx.x >> 5] = s;
    __syncthreads();
    float tot = ws[0] + ws[1] + ws[2] + ws[3];
    float denom = fmaxf(sqrtf(tot), 1e-12f);
    v.x = v.x / denom; v.y = v.y / denom; v.z = v.z / denom; v.w = v.w / denom;
    *(float4*)(p + threadIdx.x * 4) = v;
}

// ---------------------------------------------------------------------------
// Kernel 3: normalize codebook -> g_cnT (transposed), g_cnn
// ---------------------------------------------------------------------------
__global__ void norm_cb_kernel(const float* __restrict__ CB) {
    const int row = blockIdx.x;     // codeword k
    float4 v = *(const float4*)(CB + (size_t)row * E_DIM + threadIdx.x * 4);
    float s = v.x * v.x + v.y * v.y + v.z * v.z + v.w * v.w;
    #pragma unroll
    for (int o = 16; o > 0; o >>= 1) s += __shfl_xor_sync(0xFFFFFFFFu, s, o);
    __shared__ float ws[4];
    __shared__ float ws2[4];
    if ((threadIdx.x & 31) == 0) ws[threadIdx.x >> 5] = s;
    __syncthreads();
    float tot = ws[0] + ws[1] + ws[2] + ws[3];
    float denom = fmaxf(sqrtf(tot), 1e-12f);
    v.x = v.x / denom; v.y = v.y / denom; v.z = v.z / denom; v.w = v.w / denom;
    int e0 = threadIdx.x * 4;
    g_cnT[(size_t)(e0 + 0) * K_CB + row] = v.x;
    g_cnT[(size_t)(e0 + 1) * K_CB + row] = v.y;
    g_cnT[(size_t)(e0 + 2) * K_CB + row] = v.z;
    g_cnT[(size_t)(e0 + 3) * K_CB + row] = v.w;
    float s2 = v.x * v.x + v.y * v.y + v.z * v.z + v.w * v.w;
    #pragma unroll
    for (int o = 16; o > 0; o >>= 1) s2 += __shfl_xor_sync(0xFFFFFFFFu, s2, o);
    if ((threadIdx.x & 31) == 0) ws2[threadIdx.x >> 5] = s2;
    __syncthreads();
    if (threadIdx.x == 0) g_cnn[row] = ws2[0] + ws2[1] + ws2[2] + ws2[3];
}

// ---------------------------------------------------------------------------
// Kernel 4: argmax_k ( <cn_k,xn_q> - cnn[k]/2 ) == argmin distance.
// 64 queries/block, 512 threads. tx=tid&63 (8k each over 512-k chunk),
// ty=tid>>6 (8q each). 8q x 8k scalar-FFMA register tile: 64 FFMA / 4 LDS.128.
// Warp spans 32 tx at fixed ty -> xs loads are full-warp broadcasts.
// ---------------------------------------------------------------------------
#define XS_PITCH 68                 // mult of 4 -> LDS.128, conflict-free
#define EC 16                       // e's per codebook sub-tile
#define CS_PITCH 516                // 512 + 4 pad, mult of 4
#define SMEM_BYTES ((512 * XS_PITCH + EC * CS_PITCH + 512 + 128) * 4 + 128 * 4)

__global__ void __launch_bounds__(512, 1) argmin_kernel(float* __restrict__ out) {
    extern __shared__ float sm[];
    float* xs   = sm;                          // [512][68]  xs[e][q]
    float* cs   = xs + 512 * XS_PITCH;         // [16][516]  cs[e][k]
    float* cnns = cs + EC * CS_PITCH;          // [512]
    float* rv   = cnns + 512;                  // [16 warps][8 q]
    int*   ri   = (int*)(rv + 128);            // [16][8]

    const int tid  = threadIdx.x;
    const int tx   = tid & 63;     // k partition: k = tx*4+{0..3}, 256+tx*4+{0..3}
    const int ty   = tid >> 6;     // q partition: q = ty*8+{0..7}
    const int lane = tid & 31;
    const int wid  = tid >> 5;
    const int q0   = blockIdx.x * 64;

    // query tile, transposed into xs[e][q]
    #pragma unroll 4
    for (int t = 0; t < 16; t++) {
        int f = tid + t * 512;             // 0..8191
        int q = f >> 7;                    // 0..63
        int e4 = f & 127;                  // 0..127
        float4 v = *(const float4*)(g_xn + (size_t)(q0 + q) * E_DIM + e4 * 4);
        xs[(e4 * 4 + 0) * XS_PITCH + q] = v.x;
        xs[(e4 * 4 + 1) * XS_PITCH + q] = v.y;
        xs[(e4 * 4 + 2) * XS_PITCH + q] = v.z;
        xs[(e4 * 4 + 3) * XS_PITCH + q] = v.w;
    }

    float bestv[8];
    int   besti[8];
    #pragma unroll
    for (int i = 0; i < 8; i++) { bestv[i] = -INFINITY; besti[i] = 0; }

    for (int kc = 0; kc < K_CB; kc += 512) {
        __syncthreads();   // xs ready (first iter) / prev kc cnns readers done
        cnns[tid] = g_cnn[kc + tid];

        float acc[8][8];
        #pragma unroll
        for (int i = 0; i < 8; i++)
            #pragma unroll
            for (int j = 0; j < 8; j++) acc[i][j] = 0.0f;

        for (int ec = 0; ec < E_DIM; ec += EC) {
            // load sub-tile: EC e-rows x 512 k, coalesced from g_cnT
            #pragma unroll
            for (int t = 0; t < 4; t++) {
                int f  = tid + t * 512;         // 0..2047
                int e  = f >> 7;                // 0..15
                int k4 = f & 127;               // 0..127
                float4 v = *(const float4*)(g_cnT + (size_t)(ec + e) * K_CB +
                                            kc + k4 * 4);
                *(float4*)(cs + e * CS_PITCH + k4 * 4) = v;
            }
            __syncthreads();

            #pragma unroll 2
            for (int e = 0; e < EC; e++) {
                const float* xrow = xs + (ec + e) * XS_PITCH + ty * 8;
                float4 x0 = *(const float4*)(xrow);        // warp broadcast
                float4 x1 = *(const float4*)(xrow + 4);    // warp broadcast
                float4 c0 = *(const float4*)(cs + e * CS_PITCH + tx * 4);
                float4 c1 = *(const float4*)(cs + e * CS_PITCH + 256 + tx * 4);
                float xa[8] = {x0.x, x0.y, x0.z, x0.w, x1.x, x1.y, x1.z, x1.w};
                float cb[8] = {c0.x, c0.y, c0.z, c0.w, c1.x, c1.y, c1.z, c1.w};
                #pragma unroll
                for (int i = 0; i < 8; i++)
                    #pragma unroll
                    for (int j = 0; j < 8; j++)
                        acc[i][j] = fmaf(xa[i], cb[j], acc[i][j]);
            }
            __syncthreads();
        }

        // score update: maximize dot - cnn/2; strict > keeps earliest index
        #pragma unroll
        for (int i = 0; i < 8; i++) {
            #pragma unroll
            for (int j = 0; j < 8; j++) {
                int kk = (j < 4) ? (tx * 4 + j) : (256 + tx * 4 + (j - 4));
                float s = acc[i][j] - 0.5f * cnns[kk];
                if (s > bestv[i]) { bestv[i] = s; besti[i] = kc + kk; }
            }
        }
    }

    // warp reduce (ty constant within warp -> same 8 q's on all lanes)
    #pragma unroll
    for (int i = 0; i < 8; i++) {
        float v = bestv[i]; int ix = besti[i];
        #pragma unroll
        for (int o = 16; o > 0; o >>= 1) {
            float ov = __shfl_xor_sync(0xFFFFFFFFu, v, o);
            int   oi = __shfl_xor_sync(0xFFFFFFFFu, ix, o);
            if (ov > v || (ov == v && oi < ix)) { v = ov; ix = oi; }
        }
        if (lane == 0) { rv[wid * 8 + i] = v; ri[wid * 8 + i] = ix; }
    }
    __syncthreads();
    // combine the 2 warps per ty (warps 2*ty and 2*ty+1)
    if (tid < 64) {
        int q   = tid;
        int qty = q >> 3;
        int qi  = q & 7;
        int w0 = qty * 2, w1 = qty * 2 + 1;
        float v0 = rv[w0 * 8 + qi]; int i0 = ri[w0 * 8 + qi];
        float v1 = rv[w1 * 8 + qi]; int i1 = ri[w1 * 8 + qi];
        int bi = (v1 > v0 || (v1 == v0 && i1 < i0)) ? i1 : i0;
        out[q0 + q] = (float)bi;   // output dtype: float32
    }
}

// ---------------------------------------------------------------------------
extern "C" void kernel_launch(void* const* d_in, const int* in_sizes, int n_in,
                              void* d_out, int out_size) {
    const float* x  = nullptr;
    const float* w  = nullptr;
    const float* cb = nullptr;
    for (int i = 0; i < n_in; i++) {
        if (in_sizes[i] == M_TOT * D_IN)       x  = (const float*)d_in[i];
        else if (in_sizes[i] == D_IN * E_DIM)  w  = (const float*)d_in[i];
        else if (in_sizes[i] == K_CB * E_DIM)  cb = (const float*)d_in[i];
    }
    float* out = (float*)d_out;

    dim3 g1(E_DIM / 64, M_TOT / 128);   // (8, 128)
    proj_gemm_kernel<<<g1, 256>>>(x, w);
    norm_x_kernel<<<M_TOT, 128>>>();
    norm_cb_kernel<<<K_CB, 128>>>(cb);

    cudaFuncSetAttribute(argmin_kernel,
                         cudaFuncAttributeMaxDynamicSharedMemorySize, SMEM_BYTES);
    argmin_kernel<<<M_TOT / 64, 512, SMEM_BYTES>>>(out);
}

// round 10
// speedup vs baseline: 1.7406x; 1.0250x over previous
#include <cuda_runtime.h>
#include <cstdint>
#include <cfloat>
#include <math.h>

#define M_TOT 16384   // B*N queries
#define D_IN  1024
#define E_DIM 512
#define K_CB  4096

// Scratch (device globals: no allocation allowed)
__device__ float g_xn[M_TOT * E_DIM];    // proj, then normalized rows (in place)
__device__ float g_cnT[E_DIM * K_CB];    // normalized codebook, TRANSPOSED [e][k]
__device__ float g_cnn[K_CB];            // sum(cn*cn) per codeword

// ---- cp.async helpers (LDGSTS) ----
__device__ __forceinline__ void cp_async16(uint32_t saddr, const void* g) {
    asm volatile("cp.async.cg.shared.global [%0], [%1], 16;"
                 :: "r"(saddr), "l"(g) : "memory");
}
__device__ __forceinline__ void cp_commit() {
    asm volatile("cp.async.commit_group;" ::: "memory");
}
template <int N> __device__ __forceinline__ void cp_wait() {
    asm volatile("cp.async.wait_group %0;" :: "n"(N) : "memory");
}

// ---------------------------------------------------------------------------
// Kernel 1: projection GEMM  g_xn[M,E] = X[M,D] @ W[D,E]   (known-good scalar)
// ---------------------------------------------------------------------------
__global__ void proj_gemm_kernel(const float* __restrict__ X,
                                 const float* __restrict__ W) {
    __shared__ float As[16 * 132];   // [k][m], padded
    __shared__ float Bs[16 * 64];    // [k][n]
    const int tx = threadIdx.x & 15;
    const int ty = threadIdx.x >> 4;
    const int m0 = blockIdx.y * 128;
    const int n0 = blockIdx.x * 64;

    float acc[8][4];
    #pragma unroll
    for (int i = 0; i < 8; i++)
        #pragma unroll
        for (int j = 0; j < 4; j++) acc[i][j] = 0.0f;

    for (int kt = 0; kt < D_IN; kt += 16) {
        #pragma unroll
        for (int t = 0; t < 2; t++) {
            int f   = threadIdx.x * 2 + t;   // 0..511
            int row = f >> 2;                // 0..127
            int c4  = f & 3;                 // 0..3
            float4 v = *(const float4*)(X + (size_t)(m0 + row) * D_IN + kt + c4 * 4);
            As[(c4 * 4 + 0) * 132 + row] = v.x;
            As[(c4 * 4 + 1) * 132 + row] = v.y;
            As[(c4 * 4 + 2) * 132 + row] = v.z;
            As[(c4 * 4 + 3) * 132 + row] = v.w;
        }
        {
            int f  = threadIdx.x;            // 0..255
            int k  = f >> 4;
            int c4 = f & 15;
            float4 v = *(const float4*)(W + (size_t)(kt + k) * E_DIM + n0 + c4 * 4);
            *(float4*)(Bs + k * 64 + c4 * 4) = v;
        }
        __syncthreads();

        #pragma unroll
        for (int k = 0; k < 16; k++) {
            float4 a0 = *(const float4*)(As + k * 132 + ty * 8);
            float4 a1 = *(const float4*)(As + k * 132 + ty * 8 + 4);
            float4 b  = *(const float4*)(Bs + k * 64 + tx * 4);
            float a[8] = {a0.x, a0.y, a0.z, a0.w, a1.x, a1.y, a1.z, a1.w};
            float bb[4] = {b.x, b.y, b.z, b.w};
            #pragma unroll
            for (int i = 0; i < 8; i++)
                #pragma unroll
                for (int j = 0; j < 4; j++)
                    acc[i][j] = fmaf(a[i], bb[j], acc[i][j]);
        }
        __syncthreads();
    }

    #pragma unroll
    for (int i = 0; i < 8; i++) {
        float4 v = make_float4(acc[i][0], acc[i][1], acc[i][2], acc[i][3]);
        *(float4*)(g_xn + (size_t)(m0 + ty * 8 + i) * E_DIM + n0 + tx * 4) = v;
    }
}

// ---------------------------------------------------------------------------
// Kernel 2: normalize rows of g_xn in place
// ---------------------------------------------------------------------------
__global__ void norm_x_kernel() {
    const int row = blockIdx.x;
    float* p = g_xn + (size_t)row * E_DIM;
    float4 v = *(float4*)(p + threadIdx.x * 4);
    float s = v.x * v.x + v.y * v.y + v.z * v.z + v.w * v.w;
    #pragma unroll
    for (int o = 16; o > 0; o >>= 1) s += __shfl_xor_sync(0xFFFFFFFFu, s, o);
    __shared__ float ws[4];
    if ((threadIdx.x & 31) == 0) ws[threadIdx.x >> 5] = s;
    __syncthreads();
    float tot = ws[0] + ws[1] + ws[2] + ws[3];
    float denom = fmaxf(sqrtf(tot), 1e-12f);
    v.x = v.x / denom; v.y = v.y / denom; v.z = v.z / denom; v.w = v.w / denom;
    *(float4*)(p + threadIdx.x * 4) = v;
}

// ---------------------------------------------------------------------------
// Kernel 3: normalize codebook -> g_cnT (transposed), g_cnn
// ---------------------------------------------------------------------------
__global__ void norm_cb_kernel(const float* __restrict__ CB) {
    const int row = blockIdx.x;     // codeword k
    float4 v = *(const float4*)(CB + (size_t)row * E_DIM + threadIdx.x * 4);
    float s = v.x * v.x + v.y * v.y + v.z * v.z + v.w * v.w;
    #pragma unroll
    for (int o = 16; o > 0; o >>= 1) s += __shfl_xor_sync(0xFFFFFFFFu, s, o);
    __shared__ float ws[4];
    __shared__ float ws2[4];
    if ((threadIdx.x & 31) == 0) ws[threadIdx.x >> 5] = s;
    __syncthreads();
    float tot = ws[0] + ws[1] + ws[2] + ws[3];
    float denom = fmaxf(sqrtf(tot), 1e-12f);
    v.x = v.x / denom; v.y = v.y / denom; v.z = v.z / denom; v.w = v.w / denom;
    int e0 = threadIdx.x * 4;
    g_cnT[(size_t)(e0 + 0) * K_CB + row] = v.x;
    g_cnT[(size_t)(e0 + 1) * K_CB + row] = v.y;
    g_cnT[(size_t)(e0 + 2) * K_CB + row] = v.z;
    g_cnT[(size_t)(e0 + 3) * K_CB + row] = v.w;
    float s2 = v.x * v.x + v.y * v.y + v.z * v.z + v.w * v.w;
    #pragma unroll
    for (int o = 16; o > 0; o >>= 1) s2 += __shfl_xor_sync(0xFFFFFFFFu, s2, o);
    if ((threadIdx.x & 31) == 0) ws2[threadIdx.x >> 5] = s2;
    __syncthreads();
    if (threadIdx.x == 0) g_cnn[row] = ws2[0] + ws2[1] + ws2[2] + ws2[3];
}

// ---------------------------------------------------------------------------
// Kernel 4: argmax_k ( <cn_k,xn_q> - cnn[k]/2 ) == argmin distance.
// 64 queries/block, 512 threads, 8q x 8k register tile (scalar FFMA).
// Codebook streamed via 3-stage cp.async pipeline, 8-e subtiles,
// ONE __syncthreads per subtile. Fetch of it+2 issued AFTER the barrier,
// so the recycled buffer (it+2)%3 == (it-1)%3 is provably drained.
// ---------------------------------------------------------------------------
#define XS_PITCH 68                 // mult of 4 -> LDS.128
#define EC 8                        // e's per codebook sub-tile
#define NTILE (E_DIM / EC)          // 64 subtiles per k-chunk
#define CS_PITCH 516                // 512 + 4 pad
#define CS_BUF (EC * CS_PITCH)
#define SMEM_BYTES ((512 * XS_PITCH + 3 * CS_BUF + 512 + 128) * 4 + 128 * 4)

__global__ void __launch_bounds__(512, 1) argmin_kernel(float* __restrict__ out) {
    extern __shared__ float sm[];
    float* xs   = sm;                          // [512][68]  xs[e][q]
    float* cs   = xs + 512 * XS_PITCH;         // 3 x [8][516]  cs[e][k]
    float* cnns = cs + 3 * CS_BUF;             // [512]
    float* rv   = cnns + 512;                  // [16 warps][8 q]
    int*   ri   = (int*)(rv + 128);            // [16][8]

    const int tid  = threadIdx.x;
    const int tx   = tid & 63;     // k partition: k = tx*4+{0..3}, 256+tx*4+{0..3}
    const int ty   = tid >> 6;     // q partition: q = ty*8+{0..7}
    const int lane = tid & 31;
    const int wid  = tid >> 5;
    const int q0   = blockIdx.x * 64;

    // cp.async lanes for codebook subtiles (2 x 16B per thread)
    const int ld_e  = tid >> 7;        // 0..3  (+4 for t=1)
    const int ld_k4 = tid & 127;       // 0..127
    const uint32_t cs_base = (uint32_t)__cvta_generic_to_shared(cs);

    // query tile, transposed into xs[e][q]
    #pragma unroll 4
    for (int t = 0; t < 16; t++) {
        int f = tid + t * 512;             // 0..8191
        int q = f >> 7;                    // 0..63
        int e4 = f & 127;                  // 0..127
        float4 v = *(const float4*)(g_xn + (size_t)(q0 + q) * E_DIM + e4 * 4);
        xs[(e4 * 4 + 0) * XS_PITCH + q] = v.x;
        xs[(e4 * 4 + 1) * XS_PITCH + q] = v.y;
        xs[(e4 * 4 + 2) * XS_PITCH + q] = v.z;
        xs[(e4 * 4 + 3) * XS_PITCH + q] = v.w;
    }

    float bestv[8];
    int   besti[8];
    #pragma unroll
    for (int i = 0; i < 8; i++) { bestv[i] = -INFINITY; besti[i] = 0; }

    for (int kc = 0; kc < K_CB; kc += 512) {
        __syncthreads();   // xs ready (first kc) / all prev-kc compute+reads done
        cnns[tid] = g_cnn[kc + tid];

        // prologue: async-load subtiles 0 and 1 (buffers 0, 1)
        #pragma unroll
        for (int it = 0; it < 2; it++) {
            #pragma unroll
            for (int t = 0; t < 2; t++) {
                int e = ld_e + t * 4;
                cp_async16(cs_base + ((it % 3) * CS_BUF + e * CS_PITCH + ld_k4 * 4) * 4,
                           g_cnT + (size_t)(it * EC + e) * K_CB + kc + ld_k4 * 4);
            }
            cp_commit();
        }

        float acc[8][8];
        #pragma unroll
        for (int i = 0; i < 8; i++)
            #pragma unroll
            for (int j = 0; j < 8; j++) acc[i][j] = 0.0f;

        for (int it = 0; it < NTILE; it++) {
            // wait for subtile it (this thread's copies), then block-wide barrier:
            // after it, tile it is fully visible AND all warps finished compute it-1.
            if (it < NTILE - 1) { cp_wait<1>(); } else { cp_wait<0>(); }
            __syncthreads();

            // NOW safe to overwrite buffer (it+2)%3 == (it-1)%3
            if (it < NTILE - 2) {
                int nt = it + 2;
                #pragma unroll
                for (int t = 0; t < 2; t++) {
                    int e = ld_e + t * 4;
                    cp_async16(cs_base + ((nt % 3) * CS_BUF + e * CS_PITCH + ld_k4 * 4) * 4,
                               g_cnT + (size_t)(nt * EC + e) * K_CB + kc + ld_k4 * 4);
                }
                cp_commit();
            }

            const float* cur = cs + (it % 3) * CS_BUF;
            #pragma unroll
            for (int e = 0; e < EC; e++) {
                const float* xrow = xs + (it * EC + e) * XS_PITCH + ty * 8;
                float4 x0 = *(const float4*)(xrow);        // warp broadcast
                float4 x1 = *(const float4*)(xrow + 4);    // warp broadcast
                float4 c0 = *(const float4*)(cur + e * CS_PITCH + tx * 4);
                float4 c1 = *(const float4*)(cur + e * CS_PITCH + 256 + tx * 4);
                float xa[8] = {x0.x, x0.y, x0.z, x0.w, x1.x, x1.y, x1.z, x1.w};
                float cb[8] = {c0.x, c0.y, c0.z, c0.w, c1.x, c1.y, c1.z, c1.w};
                #pragma unroll
                for (int i = 0; i < 8; i++)
                    #pragma unroll
                    for (int j = 0; j < 8; j++)
                        acc[i][j] = fmaf(xa[i], cb[j], acc[i][j]);
            }
        }

        // score update: maximize dot - cnn/2; strict > keeps earliest index
        #pragma unroll
        for (int i = 0; i < 8; i++) {
            #pragma unroll
            for (int j = 0; j < 8; j++) {
                int kk = (j < 4) ? (tx * 4 + j) : (256 + tx * 4 + (j - 4));
                float s = acc[i][j] - 0.5f * cnns[kk];
                if (s > bestv[i]) { bestv[i] = s; besti[i] = kc + kk; }
            }
        }
    }

    // warp reduce (ty constant within warp -> same 8 q's on all lanes)
    #pragma unroll
    for (int i = 0; i < 8; i++) {
        float v = bestv[i]; int ix = besti[i];
        #pragma unroll
        for (int o = 16; o > 0; o >>= 1) {
            float ov = __shfl_xor_sync(0xFFFFFFFFu, v, o);
            int   oi = __shfl_xor_sync(0xFFFFFFFFu, ix, o);
            if (ov > v || (ov == v && oi < ix)) { v = ov; ix = oi; }
        }
        if (lane == 0) { rv[wid * 8 + i] = v; ri[wid * 8 + i] = ix; }
    }
    __syncthreads();
    // combine the 2 warps per ty (warps 2*ty and 2*ty+1)
    if (tid < 64) {
        int q   = tid;
        int qty = q >> 3;
        int qi  = q & 7;
        int w0 = qty * 2, w1 = qty * 2 + 1;
        float v0 = rv[w0 * 8 + qi]; int i0 = ri[w0 * 8 + qi];
        float v1 = rv[w1 * 8 + qi]; int i1 = ri[w1 * 8 + qi];
        int bi = (v1 > v0 || (v1 == v0 && i1 < i0)) ? i1 : i0;
        out[q0 + q] = (float)bi;   // output dtype: float32
    }
}

// ---------------------------------------------------------------------------
extern "C" void kernel_launch(void* const* d_in, const int* in_sizes, int n_in,
                              void* d_out, int out_size) {
    const float* x  = nullptr;
    const float* w  = nullptr;
    const float* cb = nullptr;
    for (int i = 0; i < n_in; i++) {
        if (in_sizes[i] == M_TOT * D_IN)       x  = (const float*)d_in[i];
        else if (in_sizes[i] == D_IN * E_DIM)  w  = (const float*)d_in[i];
        else if (in_sizes[i] == K_CB * E_DIM)  cb = (const float*)d_in[i];
    }
    float* out = (float*)d_out;

    dim3 g1(E_DIM / 64, M_TOT / 128);   // (8, 128)
    proj_gemm_kernel<<<g1, 256>>>(x, w);
    norm_x_kernel<<<M_TOT, 128>>>();
    norm_cb_kernel<<<K_CB, 128>>>(cb);

    cudaFuncSetAttribute(argmin_kernel,
                         cudaFuncAttributeMaxDynamicSharedMemorySize, SMEM_BYTES);
    argmin_kernel<<<M_TOT / 64, 512, SMEM_BYTES>>>(out);
}

// round 11
// speedup vs baseline: 1.8947x; 1.0885x over previous
#include <cuda_runtime.h>
#include <cstdint>
#include <cfloat>
#include <math.h>

#define M_TOT 16384   // B*N queries
#define D_IN  1024
#define E_DIM 512
#define K_CB  4096

// Scratch (device globals: no allocation allowed)
__device__ float g_xn[M_TOT * E_DIM];    // proj, then normalized rows (in place)
__device__ float g_cnT[E_DIM * K_CB];    // normalized codebook, TRANSPOSED [e][k]
__device__ float g_cnn[K_CB];            // sum(cn*cn) per codeword

// ---- cp.async helpers (LDGSTS) ----
__device__ __forceinline__ void cp_async16(uint32_t saddr, const void* g) {
    asm volatile("cp.async.cg.shared.global [%0], [%1], 16;"
                 :: "r"(saddr), "l"(g) : "memory");
}
__device__ __forceinline__ void cp_commit() {
    asm volatile("cp.async.commit_group;" ::: "memory");
}
template <int N> __device__ __forceinline__ void cp_wait() {
    asm volatile("cp.async.wait_group %0;" :: "n"(N) : "memory");
}

// ---------------------------------------------------------------------------
// Kernel 1: projection GEMM  g_xn[M,E] = X[M,D] @ W[D,E]
// BM=128, BN=64, BK=32, 256 threads, 8x4 micro-tile (1024 FFMA per 2 barriers)
// ---------------------------------------------------------------------------
__global__ void proj_gemm_kernel(const float* __restrict__ X,
                                 const float* __restrict__ W) {
    __shared__ float As[32 * 132];   // [k][m], padded
    __shared__ float Bs[32 * 64];    // [k][n]
    const int tx = threadIdx.x & 15;
    const int ty = threadIdx.x >> 4;
    const int m0 = blockIdx.y * 128;
    const int n0 = blockIdx.x * 64;

    float acc[8][4];
    #pragma unroll
    for (int i = 0; i < 8; i++)
        #pragma unroll
        for (int j = 0; j < 4; j++) acc[i][j] = 0.0f;

    for (int kt = 0; kt < D_IN; kt += 32) {
        // A tile 128x32 -> As[k][m] (transposed); 1024 float4 / 256 thr = 4 each
        #pragma unroll
        for (int t = 0; t < 4; t++) {
            int f   = threadIdx.x + t * 256;   // 0..1023
            int row = f >> 3;                  // 0..127
            int c4  = f & 7;                   // 0..7
            float4 v = *(const float4*)(X + (size_t)(m0 + row) * D_IN + kt + c4 * 4);
            As[(c4 * 4 + 0) * 132 + row] = v.x;
            As[(c4 * 4 + 1) * 132 + row] = v.y;
            As[(c4 * 4 + 2) * 132 + row] = v.z;
            As[(c4 * 4 + 3) * 132 + row] = v.w;
        }
        // B tile 32x64; 512 float4 / 256 thr = 2 each
        #pragma unroll
        for (int t = 0; t < 2; t++) {
            int f  = threadIdx.x + t * 256;    // 0..511
            int k  = f >> 4;                   // 0..31
            int c4 = f & 15;                   // 0..15
            float4 v = *(const float4*)(W + (size_t)(kt + k) * E_DIM + n0 + c4 * 4);
            *(float4*)(Bs + k * 64 + c4 * 4) = v;
        }
        __syncthreads();

        #pragma unroll
        for (int k = 0; k < 32; k++) {
            float4 a0 = *(const float4*)(As + k * 132 + ty * 8);
            float4 a1 = *(const float4*)(As + k * 132 + ty * 8 + 4);
            float4 b  = *(const float4*)(Bs + k * 64 + tx * 4);
            float a[8] = {a0.x, a0.y, a0.z, a0.w, a1.x, a1.y, a1.z, a1.w};
            float bb[4] = {b.x, b.y, b.z, b.w};
            #pragma unroll
            for (int i = 0; i < 8; i++)
                #pragma unroll
                for (int j = 0; j < 4; j++)
                    acc[i][j] = fmaf(a[i], bb[j], acc[i][j]);
        }
        __syncthreads();
    }

    #pragma unroll
    for (int i = 0; i < 8; i++) {
        float4 v = make_float4(acc[i][0], acc[i][1], acc[i][2], acc[i][3]);
        *(float4*)(g_xn + (size_t)(m0 + ty * 8 + i) * E_DIM + n0 + tx * 4) = v;
    }
}

// ---------------------------------------------------------------------------
// Kernel 2: normalize rows of g_xn in place
// ---------------------------------------------------------------------------
__global__ void norm_x_kernel() {
    const int row = blockIdx.x;
    float* p = g_xn + (size_t)row * E_DIM;
    float4 v = *(float4*)(p + threadIdx.x * 4);
    float s = v.x * v.x + v.y * v.y + v.z * v.z + v.w * v.w;
    #pragma unroll
    for (int o = 16; o > 0; o >>= 1) s += __shfl_xor_sync(0xFFFFFFFFu, s, o);
    __shared__ float ws[4];
    if ((threadIdx.x & 31) == 0) ws[threadIdx.x >> 5] = s;
    __syncthreads();
    float tot = ws[0] + ws[1] + ws[2] + ws[3];
    float denom = fmaxf(sqrtf(tot), 1e-12f);
    v.x = v.x / denom; v.y = v.y / denom; v.z = v.z / denom; v.w = v.w / denom;
    *(float4*)(p + threadIdx.x * 4) = v;
}

// ---------------------------------------------------------------------------
// Kernel 3: normalize codebook -> g_cnT (transposed), g_cnn
// ---------------------------------------------------------------------------
__global__ void norm_cb_kernel(const float* __restrict__ CB) {
    const int row = blockIdx.x;     // codeword k
    float4 v = *(const float4*)(CB + (size_t)row * E_DIM + threadIdx.x * 4);
    float s = v.x * v.x + v.y * v.y + v.z * v.z + v.w * v.w;
    #pragma unroll
    for (int o = 16; o > 0; o >>= 1) s += __shfl_xor_sync(0xFFFFFFFFu, s, o);
    __shared__ float ws[4];
    __shared__ float ws2[4];
    if ((threadIdx.x & 31) == 0) ws[threadIdx.x >> 5] = s;
    __syncthreads();
    float tot = ws[0] + ws[1] + ws[2] + ws[3];
    float denom = fmaxf(sqrtf(tot), 1e-12f);
    v.x = v.x / denom; v.y = v.y / denom; v.z = v.z / denom; v.w = v.w / denom;
    int e0 = threadIdx.x * 4;
    g_cnT[(size_t)(e0 + 0) * K_CB + row] = v.x;
    g_cnT[(size_t)(e0 + 1) * K_CB + row] = v.y;
    g_cnT[(size_t)(e0 + 2) * K_CB + row] = v.z;
    g_cnT[(size_t)(e0 + 3) * K_CB + row] = v.w;
    float s2 = v.x * v.x + v.y * v.y + v.z * v.z + v.w * v.w;
    #pragma unroll
    for (int o = 16; o > 0; o >>= 1) s2 += __shfl_xor_sync(0xFFFFFFFFu, s2, o);
    if ((threadIdx.x & 31) == 0) ws2[threadIdx.x >> 5] = s2;
    __syncthreads();
    if (threadIdx.x == 0) g_cnn[row] = ws2[0] + ws2[1] + ws2[2] + ws2[3];
}

// ---------------------------------------------------------------------------
// Kernel 4: argmax_k ( <cn_k,xn_q> - cnn[k]/2 ) == argmin distance.
// 64 queries/block, 512 threads, 8q x 8k scalar-FFMA register tile.
// FLAT pipeline over all 256 subtiles (8 kc x 32 et), EC=16 e-rows per
// subtile, 2 cp.async buffers, ONE barrier per subtile, never drains.
// cnn[4096] fully resident in smem. Epilogue every 32 subtiles (barrier-free).
// ---------------------------------------------------------------------------
#define XS_PITCH 68                 // mult of 4 -> LDS.128
#define EC 16                       // e's per codebook sub-tile
#define NSUB (8 * 32)               // total subtiles: (K/512) x (E/EC)
#define CS_PITCH 516                // 512 + 4 pad
#define CS_BUF (EC * CS_PITCH)
#define SMEM_BYTES ((512 * XS_PITCH + 2 * CS_BUF + K_CB + 128) * 4 + 128 * 4)

__global__ void __launch_bounds__(512, 1) argmin_kernel(float* __restrict__ out) {
    extern __shared__ float sm[];
    float* xs   = sm;                          // [512][68]   xs[e][q]
    float* cs   = xs + 512 * XS_PITCH;         // 2 x [16][516]  cs[e][k]
    float* cnns = cs + 2 * CS_BUF;             // [4096] (full codebook norms)
    float* rv   = cnns + K_CB;                 // [16 warps][8 q]
    int*   ri   = (int*)(rv + 128);            // [16][8]

    const int tid  = threadIdx.x;
    const int tx   = tid & 63;     // k partition: k = tx*4+{0..3}, 256+tx*4+{0..3}
    const int ty   = tid >> 6;     // q partition: q = ty*8+{0..7}
    const int lane = tid & 31;
    const int wid  = tid >> 5;
    const int q0   = blockIdx.x * 64;

    // cp.async lanes: 16 e-rows x 512 k = 2048 float4 / 512 thr = 4 each
    const int ld_e  = tid >> 7;        // 0..3 (+4t)
    const int ld_k4 = tid & 127;       // 0..127
    const uint32_t cs_base = (uint32_t)__cvta_generic_to_shared(cs);

    // full cnn -> smem (once)
    #pragma unroll
    for (int t = 0; t < 8; t++) cnns[tid + t * 512] = g_cnn[tid + t * 512];

    // query tile, transposed into xs[e][q]
    #pragma unroll 4
    for (int t = 0; t < 16; t++) {
        int f = tid + t * 512;             // 0..8191
        int q = f >> 7;                    // 0..63
        int e4 = f & 127;                  // 0..127
        float4 v = *(const float4*)(g_xn + (size_t)(q0 + q) * E_DIM + e4 * 4);
        xs[(e4 * 4 + 0) * XS_PITCH + q] = v.x;
        xs[(e4 * 4 + 1) * XS_PITCH + q] = v.y;
        xs[(e4 * 4 + 2) * XS_PITCH + q] = v.z;
        xs[(e4 * 4 + 3) * XS_PITCH + q] = v.w;
    }

    float bestv[8];
    int   besti[8];
    #pragma unroll
    for (int i = 0; i < 8; i++) { bestv[i] = -INFINITY; besti[i] = 0; }

    // prologue: fetch subtile 0 (kc=0, et=0) into buffer 0
    #pragma unroll
    for (int t = 0; t < 4; t++) {
        int e = ld_e + t * 4;
        cp_async16(cs_base + (e * CS_PITCH + ld_k4 * 4) * 4,
                   g_cnT + (size_t)e * K_CB + ld_k4 * 4);
    }
    cp_commit();

    float acc[8][8];
    #pragma unroll
    for (int i = 0; i < 8; i++)
        #pragma unroll
        for (int j = 0; j < 8; j++) acc[i][j] = 0.0f;

    for (int g = 0; g < NSUB; g++) {
        // fetch(g) complete on this thread, then publish block-wide.
        // After the barrier, all warps also finished compute(g-1), so
        // buffer (g+1)&1 (used by compute(g-1)) is drained.
        cp_wait<0>();
        __syncthreads();

        if (g + 1 < NSUB) {
            int ng  = g + 1;
            int nkc = (ng >> 5) * 512;
            int neb = (ng & 31) * EC;
            #pragma unroll
            for (int t = 0; t < 4; t++) {
                int e = ld_e + t * 4;
                cp_async16(cs_base + ((ng & 1) * CS_BUF + e * CS_PITCH + ld_k4 * 4) * 4,
                           g_cnT + (size_t)(neb + e) * K_CB + nkc + ld_k4 * 4);
            }
            cp_commit();
        }

        const float* cur   = cs + (g & 1) * CS_BUF;
        const float* xbase = xs + ((g & 31) * EC) * XS_PITCH + ty * 8;
        #pragma unroll
        for (int e = 0; e < EC; e++) {
            float4 x0 = *(const float4*)(xbase + e * XS_PITCH);        // bcast
            float4 x1 = *(const float4*)(xbase + e * XS_PITCH + 4);    // bcast
            float4 c0 = *(const float4*)(cur + e * CS_PITCH + tx * 4);
            float4 c1 = *(const float4*)(cur + e * CS_PITCH + 256 + tx * 4);
            float xa[8] = {x0.x, x0.y, x0.z, x0.w, x1.x, x1.y, x1.z, x1.w};
            float cb[8] = {c0.x, c0.y, c0.z, c0.w, c1.x, c1.y, c1.z, c1.w};
            #pragma unroll
            for (int i = 0; i < 8; i++)
                #pragma unroll
                for (int j = 0; j < 8; j++)
                    acc[i][j] = fmaf(xa[i], cb[j], acc[i][j]);
        }

        // kc boundary: score update (barrier-free), reset accumulators
        if ((g & 31) == 31) {
            int kc = (g >> 5) * 512;
            #pragma unroll
            for (int i = 0; i < 8; i++) {
                #pragma unroll
                for (int j = 0; j < 8; j++) {
                    int kk = (j < 4) ? (tx * 4 + j) : (256 + tx * 4 + (j - 4));
                    float s = acc[i][j] - 0.5f * cnns[kc + kk];
                    if (s > bestv[i]) { bestv[i] = s; besti[i] = kc + kk; }
                    acc[i][j] = 0.0f;
                }
            }
        }
    }

    // warp reduce (ty constant within warp -> same 8 q's on all lanes)
    #pragma unroll
    for (int i = 0; i < 8; i++) {
        float v = bestv[i]; int ix = besti[i];
        #pragma unroll
        for (int o = 16; o > 0; o >>= 1) {
            float ov = __shfl_xor_sync(0xFFFFFFFFu, v, o);
            int   oi = __shfl_xor_sync(0xFFFFFFFFu, ix, o);
            if (ov > v || (ov == v && oi < ix)) { v = ov; ix = oi; }
        }
        if (lane == 0) { rv[wid * 8 + i] = v; ri[wid * 8 + i] = ix; }
    }
    __syncthreads();
    // combine the 2 warps per ty (warps 2*ty and 2*ty+1)
    if (tid < 64) {
        int q   = tid;
        int qty = q >> 3;
        int qi  = q & 7;
        int w0 = qty * 2, w1 = qty * 2 + 1;
        float v0 = rv[w0 * 8 + qi]; int i0 = ri[w0 * 8 + qi];
        float v1 = rv[w1 * 8 + qi]; int i1 = ri[w1 * 8 + qi];
        int bi = (v1 > v0 || (v1 == v0 && i1 < i0)) ? i1 : i0;
        out[q0 + q] = (float)bi;   // output dtype: float32
    }
}

// ---------------------------------------------------------------------------
extern "C" void kernel_launch(void* const* d_in, const int* in_sizes, int n_in,
                              void* d_out, int out_size) {
    const float* x  = nullptr;
    const float* w  = nullptr;
    const float* cb = nullptr;
    for (int i = 0; i < n_in; i++) {
        if (in_sizes[i] == M_TOT * D_IN)       x  = (const float*)d_in[i];
        else if (in_sizes[i] == D_IN * E_DIM)  w  = (const float*)d_in[i];
        else if (in_sizes[i] == K_CB * E_DIM)  cb = (const float*)d_in[i];
    }
    float* out = (float*)d_out;

    dim3 g1(E_DIM / 64, M_TOT / 128);   // (8, 128)
    proj_gemm_kernel<<<g1, 256>>>(x, w);
    norm_x_kernel<<<M_TOT, 128>>>();
    norm_cb_kernel<<<K_CB, 128>>>(cb);

    cudaFuncSetAttribute(argmin_kernel,
                         cudaFuncAttributeMaxDynamicSharedMemorySize, SMEM_BYTES);
    argmin_kernel<<<M_TOT / 64, 512, SMEM_BYTES>>>(out);
}

// round 12
// speedup vs baseline: 1.8969x; 1.0011x over previous
#include <cuda_runtime.h>
#include <cstdint>
#include <cfloat>
#include <math.h>

#define M_TOT 16384   // B*N queries
#define D_IN  1024
#define E_DIM 512
#define K_CB  4096

// Scratch (device globals: no allocation allowed)
__device__ float g_xn[M_TOT * E_DIM];    // proj, then normalized rows (in place)
__device__ float g_cnT[E_DIM * K_CB];    // normalized codebook, TRANSPOSED [e][k]
__device__ float g_cnn[K_CB];            // sum(cn*cn) per codeword

// ---- cp.async helpers (LDGSTS) ----
__device__ __forceinline__ void cp_async16(uint32_t saddr, const void* g) {
    asm volatile("cp.async.cg.shared.global [%0], [%1], 16;"
                 :: "r"(saddr), "l"(g) : "memory");
}
__device__ __forceinline__ void cp_commit() {
    asm volatile("cp.async.commit_group;" ::: "memory");
}
template <int N> __device__ __forceinline__ void cp_wait() {
    asm volatile("cp.async.wait_group %0;" :: "n"(N) : "memory");
}

// ---------------------------------------------------------------------------
// Kernel 1: projection GEMM  g_xn[M,E] = X[M,D] @ W[D,E]
// BM=128, BN=64, BK=32, 256 threads, 8x4 micro-tile (1024 FFMA per 2 barriers)
// ---------------------------------------------------------------------------
__global__ void proj_gemm_kernel(const float* __restrict__ X,
                                 const float* __restrict__ W) {
    __shared__ float As[32 * 132];   // [k][m], padded
    __shared__ float Bs[32 * 64];    // [k][n]
    const int tx = threadIdx.x & 15;
    const int ty = threadIdx.x >> 4;
    const int m0 = blockIdx.y * 128;
    const int n0 = blockIdx.x * 64;

    float acc[8][4];
    #pragma unroll
    for (int i = 0; i < 8; i++)
        #pragma unroll
        for (int j = 0; j < 4; j++) acc[i][j] = 0.0f;

    for (int kt = 0; kt < D_IN; kt += 32) {
        // A tile 128x32 -> As[k][m] (transposed); 1024 float4 / 256 thr = 4 each
        #pragma unroll
        for (int t = 0; t < 4; t++) {
            int f   = threadIdx.x + t * 256;   // 0..1023
            int row = f >> 3;                  // 0..127
            int c4  = f & 7;                   // 0..7
            float4 v = *(const float4*)(X + (size_t)(m0 + row) * D_IN + kt + c4 * 4);
            As[(c4 * 4 + 0) * 132 + row] = v.x;
            As[(c4 * 4 + 1) * 132 + row] = v.y;
            As[(c4 * 4 + 2) * 132 + row] = v.z;
            As[(c4 * 4 + 3) * 132 + row] = v.w;
        }
        // B tile 32x64; 512 float4 / 256 thr = 2 each
        #pragma unroll
        for (int t = 0; t < 2; t++) {
            int f  = threadIdx.x + t * 256;    // 0..511
            int k  = f >> 4;                   // 0..31
            int c4 = f & 15;                   // 0..15
            float4 v = *(const float4*)(W + (size_t)(kt + k) * E_DIM + n0 + c4 * 4);
            *(float4*)(Bs + k * 64 + c4 * 4) = v;
        }
        __syncthreads();

        #pragma unroll
        for (int k = 0; k < 32; k++) {
            float4 a0 = *(const float4*)(As + k * 132 + ty * 8);
            float4 a1 = *(const float4*)(As + k * 132 + ty * 8 + 4);
            float4 b  = *(const float4*)(Bs + k * 64 + tx * 4);
            float a[8] = {a0.x, a0.y, a0.z, a0.w, a1.x, a1.y, a1.z, a1.w};
            float bb[4] = {b.x, b.y, b.z, b.w};
            #pragma unroll
            for (int i = 0; i < 8; i++)
                #pragma unroll
                for (int j = 0; j < 4; j++)
                    acc[i][j] = fmaf(a[i], bb[j], acc[i][j]);
        }
        __syncthreads();
    }

    #pragma unroll
    for (int i = 0; i < 8; i++) {
        float4 v = make_float4(acc[i][0], acc[i][1], acc[i][2], acc[i][3]);
        *(float4*)(g_xn + (size_t)(m0 + ty * 8 + i) * E_DIM + n0 + tx * 4) = v;
    }
}

// ---------------------------------------------------------------------------
// Kernel 2: normalize rows of g_xn in place
// ---------------------------------------------------------------------------
__global__ void norm_x_kernel() {
    const int row = blockIdx.x;
    float* p = g_xn + (size_t)row * E_DIM;
    float4 v = *(float4*)(p + threadIdx.x * 4);
    float s = v.x * v.x + v.y * v.y + v.z * v.z + v.w * v.w;
    #pragma unroll
    for (int o = 16; o > 0; o >>= 1) s += __shfl_xor_sync(0xFFFFFFFFu, s, o);
    __shared__ float ws[4];
    if ((threadIdx.x & 31) == 0) ws[threadIdx.x >> 5] = s;
    __syncthreads();
    float tot = ws[0] + ws[1] + ws[2] + ws[3];
    float denom = fmaxf(sqrtf(tot), 1e-12f);
    v.x = v.x / denom; v.y = v.y / denom; v.z = v.z / denom; v.w = v.w / denom;
    *(float4*)(p + threadIdx.x * 4) = v;
}

// ---------------------------------------------------------------------------
// Kernel 3: normalize codebook -> g_cnT (transposed), g_cnn
// ---------------------------------------------------------------------------
__global__ void norm_cb_kernel(const float* __restrict__ CB) {
    const int row = blockIdx.x;     // codeword k
    float4 v = *(const float4*)(CB + (size_t)row * E_DIM + threadIdx.x * 4);
    float s = v.x * v.x + v.y * v.y + v.z * v.z + v.w * v.w;
    #pragma unroll
    for (int o = 16; o > 0; o >>= 1) s += __shfl_xor_sync(0xFFFFFFFFu, s, o);
    __shared__ float ws[4];
    __shared__ float ws2[4];
    if ((threadIdx.x & 31) == 0) ws[threadIdx.x >> 5] = s;
    __syncthreads();
    float tot = ws[0] + ws[1] + ws[2] + ws[3];
    float denom = fmaxf(sqrtf(tot), 1e-12f);
    v.x = v.x / denom; v.y = v.y / denom; v.z = v.z / denom; v.w = v.w / denom;
    int e0 = threadIdx.x * 4;
    g_cnT[(size_t)(e0 + 0) * K_CB + row] = v.x;
    g_cnT[(size_t)(e0 + 1) * K_CB + row] = v.y;
    g_cnT[(size_t)(e0 + 2) * K_CB + row] = v.z;
    g_cnT[(size_t)(e0 + 3) * K_CB + row] = v.w;
    float s2 = v.x * v.x + v.y * v.y + v.z * v.z + v.w * v.w;
    #pragma unroll
    for (int o = 16; o > 0; o >>= 1) s2 += __shfl_xor_sync(0xFFFFFFFFu, s2, o);
    if ((threadIdx.x & 31) == 0) ws2[threadIdx.x >> 5] = s2;
    __syncthreads();
    if (threadIdx.x == 0) g_cnn[row] = ws2[0] + ws2[1] + ws2[2] + ws2[3];
}

// ---------------------------------------------------------------------------
// Kernel 4: argmax_k ( <cn_k,xn_q> - cnn[k]/2 ) == argmin distance.
// 64 queries/block, 512 threads, 8q x 8k scalar-FFMA register tile.
// FLAT pipeline over all 256 subtiles (8 kc x 32 et), EC=16 e-rows per
// subtile, 2 cp.async buffers, ONE barrier per subtile, never drains.
// cnn[4096] fully resident in smem. Epilogue every 32 subtiles (barrier-free).
// ---------------------------------------------------------------------------
#define XS_PITCH 68                 // mult of 4 -> LDS.128
#define EC 16                       // e's per codebook sub-tile
#define NSUB (8 * 32)               // total subtiles: (K/512) x (E/EC)
#define CS_PITCH 516                // 512 + 4 pad
#define CS_BUF (EC * CS_PITCH)
#define SMEM_BYTES ((512 * XS_PITCH + 2 * CS_BUF + K_CB + 128) * 4 + 128 * 4)

__global__ void __launch_bounds__(512, 1) argmin_kernel(float* __restrict__ out) {
    extern __shared__ float sm[];
    float* xs   = sm;                          // [512][68]   xs[e][q]
    float* cs   = xs + 512 * XS_PITCH;         // 2 x [16][516]  cs[e][k]
    float* cnns = cs + 2 * CS_BUF;             // [4096] (full codebook norms)
    float* rv   = cnns + K_CB;                 // [16 warps][8 q]
    int*   ri   = (int*)(rv + 128);            // [16][8]

    const int tid  = threadIdx.x;
    const int tx   = tid & 63;     // k partition: k = tx*4+{0..3}, 256+tx*4+{0..3}
    const int ty   = tid >> 6;     // q partition: q = ty*8+{0..7}
    const int lane = tid & 31;
    const int wid  = tid >> 5;
    const int q0   = blockIdx.x * 64;

    // cp.async lanes: 16 e-rows x 512 k = 2048 float4 / 512 thr = 4 each
    const int ld_e  = tid >> 7;        // 0..3 (+4t)
    const int ld_k4 = tid & 127;       // 0..127
    const uint32_t cs_base = (uint32_t)__cvta_generic_to_shared(cs);

    // full cnn -> smem (once)
    #pragma unroll
    for (int t = 0; t < 8; t++) cnns[tid + t * 512] = g_cnn[tid + t * 512];

    // query tile, transposed into xs[e][q]
    #pragma unroll 4
    for (int t = 0; t < 16; t++) {
        int f = tid + t * 512;             // 0..8191
        int q = f >> 7;                    // 0..63
        int e4 = f & 127;                  // 0..127
        float4 v = *(const float4*)(g_xn + (size_t)(q0 + q) * E_DIM + e4 * 4);
        xs[(e4 * 4 + 0) * XS_PITCH + q] = v.x;
        xs[(e4 * 4 + 1) * XS_PITCH + q] = v.y;
        xs[(e4 * 4 + 2) * XS_PITCH + q] = v.z;
        xs[(e4 * 4 + 3) * XS_PITCH + q] = v.w;
    }

    float bestv[8];
    int   besti[8];
    #pragma unroll
    for (int i = 0; i < 8; i++) { bestv[i] = -INFINITY; besti[i] = 0; }

    // prologue: fetch subtile 0 (kc=0, et=0) into buffer 0
    #pragma unroll
    for (int t = 0; t < 4; t++) {
        int e = ld_e + t * 4;
        cp_async16(cs_base + (e * CS_PITCH + ld_k4 * 4) * 4,
                   g_cnT + (size_t)e * K_CB + ld_k4 * 4);
    }
    cp_commit();

    float acc[8][8];
    #pragma unroll
    for (int i = 0; i < 8; i++)
        #pragma unroll
        for (int j = 0; j < 8; j++) acc[i][j] = 0.0f;

    for (int g = 0; g < NSUB; g++) {
        // fetch(g) complete on this thread, then publish block-wide.
        // After the barrier, all warps also finished compute(g-1), so
        // buffer (g+1)&1 (used by compute(g-1)) is drained.
        cp_wait<0>();
        __syncthreads();

        if (g + 1 < NSUB) {
            int ng  = g + 1;
            int nkc = (ng >> 5) * 512;
            int neb = (ng & 31) * EC;
            #pragma unroll
            for (int t = 0; t < 4; t++) {
                int e = ld_e + t * 4;
                cp_async16(cs_base + ((ng & 1) * CS_BUF + e * CS_PITCH + ld_k4 * 4) * 4,
                           g_cnT + (size_t)(neb + e) * K_CB + nkc + ld_k4 * 4);
            }
            cp_commit();
        }

        const float* cur   = cs + (g & 1) * CS_BUF;
        const float* xbase = xs + ((g & 31) * EC) * XS_PITCH + ty * 8;
        #pragma unroll
        for (int e = 0; e < EC; e++) {
            float4 x0 = *(const float4*)(xbase + e * XS_PITCH);        // bcast
            float4 x1 = *(const float4*)(xbase + e * XS_PITCH + 4);    // bcast
            float4 c0 = *(const float4*)(cur + e * CS_PITCH + tx * 4);
            float4 c1 = *(const float4*)(cur + e * CS_PITCH + 256 + tx * 4);
            float xa[8] = {x0.x, x0.y, x0.z, x0.w, x1.x, x1.y, x1.z, x1.w};
            float cb[8] = {c0.x, c0.y, c0.z, c0.w, c1.x, c1.y, c1.z, c1.w};
            #pragma unroll
            for (int i = 0; i < 8; i++)
                #pragma unroll
                for (int j = 0; j < 8; j++)
                    acc[i][j] = fmaf(xa[i], cb[j], acc[i][j]);
        }

        // kc boundary: score update (barrier-free), reset accumulators
        if ((g & 31) == 31) {
            int kc = (g >> 5) * 512;
            #pragma unroll
            for (int i = 0; i < 8; i++) {
                #pragma unroll
                for (int j = 0; j < 8; j++) {
                    int kk = (j < 4) ? (tx * 4 + j) : (256 + tx * 4 + (j - 4));
                    float s = acc[i][j] - 0.5f * cnns[kc + kk];
                    if (s > bestv[i]) { bestv[i] = s; besti[i] = kc + kk; }
                    acc[i][j] = 0.0f;
                }
            }
        }
    }

    // warp reduce (ty constant within warp -> same 8 q's on all lanes)
    #pragma unroll
    for (int i = 0; i < 8; i++) {
        float v = bestv[i]; int ix = besti[i];
        #pragma unroll
        for (int o = 16; o > 0; o >>= 1) {
            float ov = __shfl_xor_sync(0xFFFFFFFFu, v, o);
            int   oi = __shfl_xor_sync(0xFFFFFFFFu, ix, o);
            if (ov > v || (ov == v && oi < ix)) { v = ov; ix = oi; }
        }
        if (lane == 0) { rv[wid * 8 + i] = v; ri[wid * 8 + i] = ix; }
    }
    __syncthreads();
    // combine the 2 warps per ty (warps 2*ty and 2*ty+1)
    if (tid < 64) {
        int q   = tid;
        int qty = q >> 3;
        int qi  = q & 7;
        int w0 = qty * 2, w1 = qty * 2 + 1;
        float v0 = rv[w0 * 8 + qi]; int i0 = ri[w0 * 8 + qi];
        float v1 = rv[w1 * 8 + qi]; int i1 = ri[w1 * 8 + qi];
        int bi = (v1 > v0 || (v1 == v0 && i1 < i0)) ? i1 : i0;
        out[q0 + q] = (float)bi;   // output dtype: float32
    }
}

// ---------------------------------------------------------------------------
extern "C" void kernel_launch(void* const* d_in, const int* in_sizes, int n_in,
                              void* d_out, int out_size) {
    const float* x  = nullptr;
    const float* w  = nullptr;
    const float* cb = nullptr;
    for (int i = 0; i < n_in; i++) {
        if (in_sizes[i] == M_TOT * D_IN)       x  = (const float*)d_in[i];
        else if (in_sizes[i] == D_IN * E_DIM)  w  = (const float*)d_in[i];
        else if (in_sizes[i] == K_CB * E_DIM)  cb = (const float*)d_in[i];
    }
    float* out = (float*)d_out;

    dim3 g1(E_DIM / 64, M_TOT / 128);   // (8, 128)
    proj_gemm_kernel<<<g1, 256>>>(x, w);
    norm_x_kernel<<<M_TOT, 128>>>();
    norm_cb_kernel<<<K_CB, 128>>>(cb);

    cudaFuncSetAttribute(argmin_kernel,
                         cudaFuncAttributeMaxDynamicSharedMemorySize, SMEM_BYTES);
    argmin_kernel<<<M_TOT / 64, 512, SMEM_BYTES>>>(out);
}